// round 11
// baseline (speedup 1.0000x reference)
#include <cuda_runtime.h>
#include <cuda_fp16.h>
#include <mma.h>
#include <cstdint>

using namespace nvcuda;

#define NPOS  1008
#define KPAD  768
#define NCAP  288

// ---------------- device scratch ----------------
__device__ float  g_wavT[512 * 128];                // wavT[k][o]
__device__ __half g_xhf[(size_t)4096 * 1024];       // x fp16, padded stride 1024 (tail zero)
__device__ __half g_cwhf[256 * 2048];               // conv_w fp16, k-index = o + 128*k2
__device__ __half g_W2T[768 * 2048];                // wav im2col: [tau][o + 128*k2]
__device__ __half g_B_E[256 * KPAD];                // E[c][tau]
__device__ __half g_Bpk[144 * 128 * 16];            // packed block-diag W: [g][n][k]
__device__ float  g_P2[(size_t)4096 * 2304];        // p [b][flat=c*9+m]
__device__ __half g_UH[(size_t)4096 * 18432];       // u_hat [b][cap*64 + d*16 + o]

// ---------------- helpers ----------------
static __device__ __forceinline__ uint32_t smem_u32(const void* p) {
    uint32_t a;
    asm("{ .reg .u64 t; cvta.to.shared.u64 t, %1; cvt.u32.u64 %0, t; }" : "=r"(a) : "l"(p));
    return a;
}
static __device__ __forceinline__ void cp_async16(uint32_t dst, const void* src) {
    asm volatile("cp.async.cg.shared.global [%0], [%1], 16;" :: "r"(dst), "l"(src));
}
#define CP_COMMIT() asm volatile("cp.async.commit_group;" ::: "memory")
#define CP_WAIT(n)  asm volatile("cp.async.wait_group %0;" :: "n"(n) : "memory")

// ---------------- fused precompute: xhf | cwhf | bpk | wav ----------------
__global__ void pre1_kernel(const float* __restrict__ x, const float* __restrict__ a,
                            const float* __restrict__ w, const float* __restrict__ conv_w,
                            const float* __restrict__ Wc) {
    const int bid = blockIdx.x, tid = threadIdx.x;
    if (bid < 16384) {
        size_t i = (size_t)bid * 256 + tid;
        int b = (int)(i >> 10), pos = (int)(i & 1023);
        float v = (pos < NPOS) ? x[(size_t)b * NPOS + pos] : 0.0f;
        g_xhf[i] = __float2half_rn(v);
    } else if (bid < 18432) {
        int i = (bid - 16384) * 256 + tid;
        int c = i >> 11, j = i & 2047;
        int o = j & 127, k2 = j >> 7;
        g_cwhf[i] = __float2half_rn(conv_w[c * 2048 + o * 16 + k2]);
    } else if (bid < 19584) {
        int i = (bid - 18432) * 256 + tid;
        int g = i >> 11, rem = i & 2047;
        int n = rem >> 4, k = rem & 15;
        int capl = n >> 6, np = n & 63;
        int capk = k >> 3, ii = k & 7;
        float v = (capl == capk) ? Wc[(size_t)(2 * g + capl) * 512 + np * 8 + ii] : 0.0f;
        g_Bpk[i] = __float2half_rn(v);
    } else {
        int ob = bid - 19584;
        int o = ob >> 1, k = ((ob & 1) << 8) + tid;
        float av = fmaxf(a[o], 1e-5f);
        float t  = fmaf((float)k, 2.0f / 511.0f, -1.0f);
        float ts = t / av;
        g_wavT[k * 128 + o] = cosf(w[o] * t) * expf(-0.5f * ts * ts);
    }
}

__global__ void w2t_kernel() {
    int i = blockIdx.x * 256 + threadIdx.x;
    if (i >= 768 * 2048) return;
    int tau = i >> 11, j = i & 2047;
    int o = j & 127, k2 = j >> 7;
    int k = tau - 16 * k2;
    float v = (k >= 0 && k < 512) ? g_wavT[k * 128 + o] : 0.0f;
    g_W2T[i] = __float2half_rn(v);
}

// ---------------- compose GEMM (wmma): E[256,768] = cwhf x W2T^T, K=2048 ----------------
#define COMP_SMEM 36864
__global__ __launch_bounds__(256, 2)
void compose_wmma_kernel() {
    extern __shared__ char smem[];
    __half* As = (__half*)smem;
    __half* Bs = As + 128 * 72;
    float*  stage = (float*)smem;

    const int tid = threadIdx.x;
    const int wid = tid >> 5;
    const int wm = wid & 3, wn = wid >> 2;
    const int c0   = blockIdx.x * 128;
    const int tau0 = blockIdx.y * 128;

    const int row = tid >> 1, seg = (tid & 1) * 32;
    const __half* arow = g_cwhf + (size_t)(c0 + row) * 2048;
    const __half* brow = g_W2T + (size_t)(tau0 + row) * 2048;

    wmma::fragment<wmma::matrix_a, 16, 16, 16, __half, wmma::row_major> af[2];
    wmma::fragment<wmma::matrix_b, 16, 16, 16, __half, wmma::col_major> bf[4];
    wmma::fragment<wmma::accumulator, 16, 16, 16, float> acc[2][4];
    #pragma unroll
    for (int i = 0; i < 2; ++i)
        #pragma unroll
        for (int j = 0; j < 4; ++j)
            wmma::fill_fragment(acc[i][j], 0.0f);

    for (int chunk = 0; chunk < 32; ++chunk) {
        {
            const uint4* ap = (const uint4*)(arow + chunk * 64 + seg);
            uint4* dp = (uint4*)(As + row * 72 + seg);
            #pragma unroll
            for (int q = 0; q < 4; ++q) dp[q] = ap[q];
        }
        {
            const uint4* bp = (const uint4*)(brow + chunk * 64 + seg);
            uint4* dp = (uint4*)(Bs + row * 72 + seg);
            #pragma unroll
            for (int q = 0; q < 4; ++q) dp[q] = bp[q];
        }
        __syncthreads();
        #pragma unroll
        for (int kk = 0; kk < 4; ++kk) {
            #pragma unroll
            for (int i = 0; i < 2; ++i)
                wmma::load_matrix_sync(af[i], As + (wm*32 + i*16) * 72 + kk*16, 72);
            #pragma unroll
            for (int j = 0; j < 4; ++j)
                wmma::load_matrix_sync(bf[j], Bs + (wn*64 + j*16) * 72 + kk*16, 72);
            #pragma unroll
            for (int i = 0; i < 2; ++i)
                #pragma unroll
                for (int j = 0; j < 4; ++j)
                    wmma::mma_sync(acc[i][j], af[i], bf[j], acc[i][j]);
        }
        __syncthreads();
    }

    for (int p = 0; p < 2; ++p) {
        if (wn == p) {
            #pragma unroll
            for (int i = 0; i < 2; ++i)
                #pragma unroll
                for (int j = 0; j < 4; ++j)
                    wmma::store_matrix_sync(stage + (wm*32 + i*16) * 68 + j*16,
                                            acc[i][j], 68, wmma::mem_row_major);
        }
        __syncthreads();
        {
            int r2 = tid >> 1, cs = (tid & 1) * 32;
            const float* sp = stage + r2 * 68 + cs;
            uint4 ov[4];
            #pragma unroll
            for (int u = 0; u < 4; ++u) {
                uint32_t pk[4];
                #pragma unroll
                for (int e = 0; e < 4; ++e) {
                    __half2_raw h = __half2_raw(__floats2half2_rn(sp[u*8 + 2*e], sp[u*8 + 2*e + 1]));
                    pk[e] = h.x | ((uint32_t)h.y << 16);
                }
                ov[u] = make_uint4(pk[0], pk[1], pk[2], pk[3]);
            }
            uint4* dp = (uint4*)(g_B_E + (size_t)(c0 + r2) * KPAD + tau0 + p * 64 + cs);
            #pragma unroll
            for (int u = 0; u < 4; ++u) dp[u] = ov[u];
        }
        __syncthreads();
    }
}

// ---------------- conv GEMM v4: 8 warps, 64x64 warp tiles, cp.async 2-stage ----------------
// buf: A[128][72]h (18432) + B[256][72]h (36864) = 55296; x2 = 110592; bias[256]f = 1024
#define CONV_SMEM (110592 + 1024)
__global__ __launch_bounds__(256, 1)
void conv_wmma_kernel(const float* __restrict__ conv_b) {
    extern __shared__ char smem[];
    float*  stage = (float*)smem;               // epilogue: [128][130]f
    float*  bias  = (float*)(smem + 110592);    // [256]

    const int tid = threadIdx.x;
    const int wid = tid >> 5;                   // 0..7
    const int wm = wid & 1, wn = wid >> 1;      // wm: 2 x 64 rows, wn: 4 x 64 cols
    const int r0 = blockIdx.x * 128;

    bias[tid] = conv_b[tid];

    // A-load mapping: 4 cp/thread (128 rows x 64 halves)
    const int arow_i = tid >> 1, aseg = (tid & 1) * 32;
    const int ar = r0 + arow_i, ab = ar / 9, am = ar - 9 * ab;
    const __half* xrow = g_xhf + (size_t)ab * 1024 + 32 * am + aseg;
    // B-load mapping: 8 cp/thread (256 rows x 64 halves)
    const __half* brow = g_B_E + (size_t)tid * KPAD;

    const uint32_t sbase = smem_u32(smem);
    const uint32_t aoff = (uint32_t)(arow_i * 72 + aseg) * 2;
    const uint32_t boff = 18432 + (uint32_t)(tid * 72) * 2;

    wmma::fragment<wmma::matrix_a, 16, 16, 16, __half, wmma::row_major> af[4];
    wmma::fragment<wmma::matrix_b, 16, 16, 16, __half, wmma::col_major> bf;
    wmma::fragment<wmma::accumulator, 16, 16, 16, float> acc[4][4];
    #pragma unroll
    for (int i = 0; i < 4; ++i)
        #pragma unroll
        for (int j = 0; j < 4; ++j)
            wmma::fill_fragment(acc[i][j], 0.0f);

    {   // prefetch chunk 0 -> buf 0
        #pragma unroll
        for (int q = 0; q < 4; ++q) cp_async16(sbase + aoff + q * 16, xrow + q * 8);
        #pragma unroll
        for (int q = 0; q < 8; ++q) cp_async16(sbase + boff + q * 16, brow + q * 8);
        CP_COMMIT();
    }

    for (int chunk = 0; chunk < 12; ++chunk) {
        if (chunk < 11) {
            uint32_t bufn = ((chunk + 1) & 1) * 55296;
            const __half* xs  = xrow + (chunk + 1) * 64;
            const __half* bs2 = brow + (chunk + 1) * 64;
            #pragma unroll
            for (int q = 0; q < 4; ++q) cp_async16(sbase + bufn + aoff + q * 16, xs + q * 8);
            #pragma unroll
            for (int q = 0; q < 8; ++q) cp_async16(sbase + bufn + boff + q * 16, bs2 + q * 8);
            CP_COMMIT();
            CP_WAIT(1);
        } else {
            CP_WAIT(0);
        }
        __syncthreads();
        __half* As = (__half*)(smem + (chunk & 1) * 55296);
        __half* Bs = As + 128 * 72;
        #pragma unroll
        for (int kk = 0; kk < 4; ++kk) {
            #pragma unroll
            for (int i = 0; i < 4; ++i)
                wmma::load_matrix_sync(af[i], As + (wm*64 + i*16) * 72 + kk*16, 72);
            #pragma unroll
            for (int j = 0; j < 4; ++j) {
                wmma::load_matrix_sync(bf, Bs + (wn*64 + j*16) * 72 + kk*16, 72);
                #pragma unroll
                for (int i = 0; i < 4; ++i)
                    wmma::mma_sync(acc[i][j], af[i], bf, acc[i][j]);
            }
        }
        __syncthreads();
    }

    // ---- epilogue: two column-half passes, coalesced P2 writes ----
    const int b_first = r0 / 9;
    const int b_last  = (r0 + 127) / 9;
    for (int p = 0; p < 2; ++p) {
        if ((wn >> 1) == p) {
            #pragma unroll
            for (int i = 0; i < 4; ++i)
                #pragma unroll
                for (int j = 0; j < 4; ++j)
                    wmma::store_matrix_sync(stage + (wm*64 + i*16) * 130 + (wn & 1) * 64 + j*16,
                                            acc[i][j], 130, wmma::mem_row_major);
        }
        __syncthreads();
        for (int b = b_first; b <= b_last; ++b) {
            const int rbase = b * 9 - r0;
            float* dst = g_P2 + (size_t)b * 2304 + p * 1152;
            for (int j = tid; j < 1152; j += 256) {
                int cl = j / 9, m = j - 9 * cl;
                int rr = rbase + m;
                if (rr >= 0 && rr < 128)
                    dst[j] = stage[rr * 130 + cl] + bias[p * 128 + cl];
            }
        }
        __syncthreads();
    }
}

// ---------------- u_hat GEMM v3 ----------------
#define UHAT_SMEM (6144 + 6144 + 10240)
__global__ __launch_bounds__(256, 6)
void uhat_gemm_kernel() {
    extern __shared__ char smem[];
    __half* Aw = (__half*)smem;                  // [128][24]
    __half* Bw = (__half*)(smem + 6144);         // [128][24]
    float*  stg = (float*)(smem + 12288);        // per-warp [16][20]

    const int tid = threadIdx.x, wid = tid >> 5, lane = tid & 31;
    const int b0 = blockIdx.x * 128;
    const int g  = blockIdx.y;

    {
        int b_l = tid >> 1, capl = tid & 1;
        int b = b0 + b_l, cap = g * 2 + capl;
        const float4* pp = (const float4*)(g_P2 + (size_t)b * 2304 + cap * 8);
        float4 p0 = pp[0], p1 = pp[1];
        float sn = p0.x*p0.x + p0.y*p0.y + p0.z*p0.z + p0.w*p0.w
                 + p1.x*p1.x + p1.y*p1.y + p1.z*p1.z + p1.w*p1.w;
        float sc = (sn / (1.0f + sn)) * rsqrtf(sn + 1e-8f);
        __half2_raw h0 = __half2_raw(__floats2half2_rn(p0.x*sc, p0.y*sc));
        __half2_raw h1 = __half2_raw(__floats2half2_rn(p0.z*sc, p0.w*sc));
        __half2_raw h2 = __half2_raw(__floats2half2_rn(p1.x*sc, p1.y*sc));
        __half2_raw h3 = __half2_raw(__floats2half2_rn(p1.z*sc, p1.w*sc));
        *(uint4*)(Aw + b_l * 24 + capl * 8) =
            make_uint4(h0.x | ((uint32_t)h0.y << 16), h1.x | ((uint32_t)h1.y << 16),
                       h2.x | ((uint32_t)h2.y << 16), h3.x | ((uint32_t)h3.y << 16));
    }
    {
        int n = tid >> 1, hseg = (tid & 1) * 8;
        uint4 v = *(const uint4*)(g_Bpk + (size_t)g * 2048 + n * 16 + hseg);
        *(uint4*)(Bw + n * 24 + hseg) = v;
    }
    __syncthreads();

    wmma::fragment<wmma::matrix_a, 16, 16, 16, __half, wmma::row_major> af;
    wmma::load_matrix_sync(af, Aw + wid * 16 * 24, 24);
    float* ws = stg + wid * 320;
    const int orow = lane >> 1, ocs = (lane & 1) * 8;
    #pragma unroll
    for (int j = 0; j < 8; ++j) {
        wmma::fragment<wmma::matrix_b, 16, 16, 16, __half, wmma::col_major> bfj;
        wmma::load_matrix_sync(bfj, Bw + j * 16 * 24, 24);
        wmma::fragment<wmma::accumulator, 16, 16, 16, float> acc;
        wmma::fill_fragment(acc, 0.0f);
        wmma::mma_sync(acc, af, bfj, acc);
        wmma::store_matrix_sync(ws, acc, 20, wmma::mem_row_major);
        __syncwarp();
        {
            const float* sp = ws + orow * 20 + ocs;
            uint32_t pk[4];
            #pragma unroll
            for (int e = 0; e < 4; ++e) {
                __half2_raw h = __half2_raw(__floats2half2_rn(sp[2*e], sp[2*e + 1]));
                pk[e] = h.x | ((uint32_t)h.y << 16);
            }
            *(uint4*)(g_UH + (size_t)(b0 + wid * 16 + orow) * 18432 + g * 128 + j * 16 + ocs) =
                make_uint4(pk[0], pk[1], pk[2], pk[3]);
        }
        __syncwarp();
    }
}

// ---------------- routing v6: transposed cij for vectorized s_j ----------------
// smem: uhh 41472 | bij 4608 | cijT 4*292*4=4672 | part 2048 | vv 256
#define ROUT_SMEM (41472 + 4608 + 4672 + 2048 + 256)
__global__ __launch_bounds__(256, 4)
void routing_kernel(float* __restrict__ out, int nB) {
    extern __shared__ char smc[];
    __half* uhh = (__half*)smc;                  // [288][72]
    float* bij  = (float*)(smc + 41472);         // [1152]
    float* cijT = bij + 1152;                    // [4][292]
    float* part = cijT + 4 * 292;                // [512]
    float* vv   = part + 512;                    // [64]
    const int tid = threadIdx.x;
    const int b = blockIdx.x;

    const uint4* src = (const uint4*)(g_UH + (size_t)b * 18432);
    #pragma unroll
    for (int it = 0; it < 9; ++it) {
        int vi = tid + it * 256;
        uint4 v = src[vi];
        int cc = vi >> 3, seg = (vi & 7) * 8;
        *(uint4*)(uhh + cc * 72 + seg) = v;
    }
    __syncthreads();

    const int prt = tid >> 5, op = tid & 31;     // 8 partitions x 32 half2 lanes
    const int dd  = op >> 3;

    for (int r = 0; r < 3; ++r) {
        if (r > 0) {
            for (int j = tid; j < NCAP; j += 256) {
                float b0 = bij[j*4+0], b1 = bij[j*4+1], b2 = bij[j*4+2], b3 = bij[j*4+3];
                float mx = fmaxf(fmaxf(b0, b1), fmaxf(b2, b3));
                float e0 = __expf(b0-mx), e1 = __expf(b1-mx);
                float e2 = __expf(b2-mx), e3 = __expf(b3-mx);
                float inv = 1.0f / (e0 + e1 + e2 + e3);
                cijT[0*292 + j] = e0*inv; cijT[1*292 + j] = e1*inv;
                cijT[2*292 + j] = e2*inv; cijT[3*292 + j] = e3*inv;
            }
            __syncthreads();
        }
        {
            float a0 = 0.0f, a1 = 0.0f;
            int cb = prt * 36;
            if (r == 0) {
                #pragma unroll 4
                for (int cc = cb; cc < cb + 36; ++cc) {
                    float2 f = __half22float2(*(const __half2*)(uhh + cc * 72 + 2 * op));
                    a0 += f.x; a1 += f.y;
                }
                a0 *= 0.25f; a1 *= 0.25f;
            } else {
                const float* cwp = cijT + dd * 292 + cb;
                #pragma unroll
                for (int q = 0; q < 9; ++q) {
                    float4 cw = *(const float4*)(cwp + q * 4);
                    int cc = cb + q * 4;
                    float2 f0 = __half22float2(*(const __half2*)(uhh + (cc+0) * 72 + 2 * op));
                    float2 f1 = __half22float2(*(const __half2*)(uhh + (cc+1) * 72 + 2 * op));
                    float2 f2 = __half22float2(*(const __half2*)(uhh + (cc+2) * 72 + 2 * op));
                    float2 f3 = __half22float2(*(const __half2*)(uhh + (cc+3) * 72 + 2 * op));
                    a0 += cw.x * f0.x + cw.y * f1.x + cw.z * f2.x + cw.w * f3.x;
                    a1 += cw.x * f0.y + cw.y * f1.y + cw.z * f2.y + cw.w * f3.y;
                }
            }
            part[prt * 64 + 2 * op]     = a0;
            part[prt * 64 + 2 * op + 1] = a1;
        }
        __syncthreads();
        if (tid < 64) {
            float s = 0.0f;
            #pragma unroll
            for (int p = 0; p < 8; ++p) s += part[p * 64 + tid];
            float sq = s * s;
            #pragma unroll
            for (int off = 8; off >= 1; off >>= 1)
                sq += __shfl_xor_sync(0xffffffffu, sq, off);
            float scale = (sq / (1.0f + sq)) * rsqrtf(sq + 1e-8f);
            vv[tid] = s * scale;
        }
        __syncthreads();
        if (r < 2) {
            for (int i = tid; i < 1152; i += 256) {
                int cc = i >> 2, d2 = i & 3;
                const __half2* up = (const __half2*)(uhh + cc * 72 + d2 * 16);
                const float* vp = vv + d2 * 16;
                float agr = 0.0f;
                #pragma unroll
                for (int e = 0; e < 8; ++e) {
                    float2 f = __half22float2(up[e]);
                    agr += f.x * vp[2*e] + f.y * vp[2*e + 1];
                }
                if (r == 0) bij[i] = agr; else bij[i] += agr;
            }
            __syncthreads();
        }
    }
    if (tid < 4) {
        float sn = 0.0f;
        #pragma unroll
        for (int o = 0; o < 16; ++o) { float t = vv[tid*16+o]; sn += t*t; }
        out[b * 4 + tid] = sqrtf(sn);
    }
    float* out_cij = out + (size_t)nB * 4 + (size_t)b * 1152;
    for (int i = tid; i < 1152; i += 256)
        out_cij[i] = cijT[(i & 3) * 292 + (i >> 2)];
}

// ---------------- launcher ----------------
extern "C" void kernel_launch(void* const* d_in, const int* in_sizes, int n_in,
                              void* d_out, int out_size) {
    const float* x      = (const float*)d_in[0];
    const float* a      = (const float*)d_in[1];
    const float* w      = (const float*)d_in[2];
    const float* conv_w = (const float*)d_in[3];
    const float* conv_b = (const float*)d_in[4];
    const float* W_caps = (const float*)d_in[5];
    int nB = in_sizes[0] / NPOS;   // 4096

    cudaFuncSetAttribute(conv_wmma_kernel, cudaFuncAttributeMaxDynamicSharedMemorySize, CONV_SMEM);
    cudaFuncSetAttribute(routing_kernel,   cudaFuncAttributeMaxDynamicSharedMemorySize, ROUT_SMEM);

    pre1_kernel<<<19840, 256>>>(x, a, w, conv_w, W_caps);
    w2t_kernel<<<6144, 256>>>();
    compose_wmma_kernel<<<dim3(2, 6), 256, COMP_SMEM>>>();
    conv_wmma_kernel<<<nB * 9 / 128, 256, CONV_SMEM>>>(conv_b);
    uhat_gemm_kernel<<<dim3(nB / 128, 144), 256, UHAT_SMEM>>>();
    routing_kernel<<<nB, 256, ROUT_SMEM>>>((float*)d_out, nB);
}

// round 12
// speedup vs baseline: 1.0469x; 1.0469x over previous
#include <cuda_runtime.h>
#include <cuda_fp16.h>
#include <mma.h>
#include <cstdint>

using namespace nvcuda;

#define NPOS  1008
#define KPAD  768
#define NCAP  288

// ---------------- device scratch ----------------
__device__ float  g_wavT[512 * 128];                // wavT[k][o]
__device__ __half g_xhf[(size_t)4096 * 1024];       // x fp16, padded stride 1024 (tail zero)
__device__ __half g_cwhf[256 * 2048];               // conv_w fp16, k-index = o + 128*k2
__device__ __half g_W2T[768 * 2048];                // wav im2col: [tau][o + 128*k2]
__device__ __half g_B_E[256 * KPAD];                // E[c][tau]
__device__ __half g_Bpk[144 * 128 * 16];            // packed block-diag W: [g][n][k]
__device__ float  g_P2[(size_t)4096 * 2304];        // p [b][flat=c*9+m]
__device__ __half g_UH[(size_t)4096 * 18432];       // u_hat [b][cap*64 + d*16 + o]

// ---------------- helpers ----------------
static __device__ __forceinline__ uint32_t smem_u32(const void* p) {
    uint32_t a;
    asm("{ .reg .u64 t; cvta.to.shared.u64 t, %1; cvt.u32.u64 %0, t; }" : "=r"(a) : "l"(p));
    return a;
}
static __device__ __forceinline__ void cp_async16(uint32_t dst, const void* src) {
    asm volatile("cp.async.cg.shared.global [%0], [%1], 16;" :: "r"(dst), "l"(src));
}
#define CP_COMMIT() asm volatile("cp.async.commit_group;" ::: "memory")
#define CP_WAIT(n)  asm volatile("cp.async.wait_group %0;" :: "n"(n) : "memory")

// ---------------- fused precompute: xhf | cwhf | bpk | wav ----------------
__global__ void pre1_kernel(const float* __restrict__ x, const float* __restrict__ a,
                            const float* __restrict__ w, const float* __restrict__ conv_w,
                            const float* __restrict__ Wc) {
    const int bid = blockIdx.x, tid = threadIdx.x;
    if (bid < 16384) {
        size_t i = (size_t)bid * 256 + tid;
        int b = (int)(i >> 10), pos = (int)(i & 1023);
        float v = (pos < NPOS) ? x[(size_t)b * NPOS + pos] : 0.0f;
        g_xhf[i] = __float2half_rn(v);
    } else if (bid < 18432) {
        int i = (bid - 16384) * 256 + tid;
        int c = i >> 11, j = i & 2047;
        int o = j & 127, k2 = j >> 7;
        g_cwhf[i] = __float2half_rn(conv_w[c * 2048 + o * 16 + k2]);
    } else if (bid < 19584) {
        int i = (bid - 18432) * 256 + tid;
        int g = i >> 11, rem = i & 2047;
        int n = rem >> 4, k = rem & 15;
        int capl = n >> 6, np = n & 63;
        int capk = k >> 3, ii = k & 7;
        float v = (capl == capk) ? Wc[(size_t)(2 * g + capl) * 512 + np * 8 + ii] : 0.0f;
        g_Bpk[i] = __float2half_rn(v);
    } else {
        int ob = bid - 19584;
        int o = ob >> 1, k = ((ob & 1) << 8) + tid;
        float av = fmaxf(a[o], 1e-5f);
        float t  = fmaf((float)k, 2.0f / 511.0f, -1.0f);
        float ts = t / av;
        g_wavT[k * 128 + o] = cosf(w[o] * t) * expf(-0.5f * ts * ts);
    }
}

__global__ void w2t_kernel() {
    int i = blockIdx.x * 256 + threadIdx.x;
    if (i >= 768 * 2048) return;
    int tau = i >> 11, j = i & 2047;
    int o = j & 127, k2 = j >> 7;
    int k = tau - 16 * k2;
    float v = (k >= 0 && k < 512) ? g_wavT[k * 128 + o] : 0.0f;
    g_W2T[i] = __float2half_rn(v);
}

// ---------------- compose GEMM (wmma): E[256,768] = cwhf x W2T^T, K=2048 ----------------
#define COMP_SMEM 36864
__global__ __launch_bounds__(256, 2)
void compose_wmma_kernel() {
    extern __shared__ char smem[];
    __half* As = (__half*)smem;
    __half* Bs = As + 128 * 72;
    float*  stage = (float*)smem;

    const int tid = threadIdx.x;
    const int wid = tid >> 5;
    const int wm = wid & 3, wn = wid >> 2;
    const int c0   = blockIdx.x * 128;
    const int tau0 = blockIdx.y * 128;

    const int row = tid >> 1, seg = (tid & 1) * 32;
    const __half* arow = g_cwhf + (size_t)(c0 + row) * 2048;
    const __half* brow = g_W2T + (size_t)(tau0 + row) * 2048;

    wmma::fragment<wmma::matrix_a, 16, 16, 16, __half, wmma::row_major> af[2];
    wmma::fragment<wmma::matrix_b, 16, 16, 16, __half, wmma::col_major> bf[4];
    wmma::fragment<wmma::accumulator, 16, 16, 16, float> acc[2][4];
    #pragma unroll
    for (int i = 0; i < 2; ++i)
        #pragma unroll
        for (int j = 0; j < 4; ++j)
            wmma::fill_fragment(acc[i][j], 0.0f);

    for (int chunk = 0; chunk < 32; ++chunk) {
        {
            const uint4* ap = (const uint4*)(arow + chunk * 64 + seg);
            uint4* dp = (uint4*)(As + row * 72 + seg);
            #pragma unroll
            for (int q = 0; q < 4; ++q) dp[q] = ap[q];
        }
        {
            const uint4* bp = (const uint4*)(brow + chunk * 64 + seg);
            uint4* dp = (uint4*)(Bs + row * 72 + seg);
            #pragma unroll
            for (int q = 0; q < 4; ++q) dp[q] = bp[q];
        }
        __syncthreads();
        #pragma unroll
        for (int kk = 0; kk < 4; ++kk) {
            #pragma unroll
            for (int i = 0; i < 2; ++i)
                wmma::load_matrix_sync(af[i], As + (wm*32 + i*16) * 72 + kk*16, 72);
            #pragma unroll
            for (int j = 0; j < 4; ++j)
                wmma::load_matrix_sync(bf[j], Bs + (wn*64 + j*16) * 72 + kk*16, 72);
            #pragma unroll
            for (int i = 0; i < 2; ++i)
                #pragma unroll
                for (int j = 0; j < 4; ++j)
                    wmma::mma_sync(acc[i][j], af[i], bf[j], acc[i][j]);
        }
        __syncthreads();
    }

    for (int p = 0; p < 2; ++p) {
        if (wn == p) {
            #pragma unroll
            for (int i = 0; i < 2; ++i)
                #pragma unroll
                for (int j = 0; j < 4; ++j)
                    wmma::store_matrix_sync(stage + (wm*32 + i*16) * 68 + j*16,
                                            acc[i][j], 68, wmma::mem_row_major);
        }
        __syncthreads();
        {
            int r2 = tid >> 1, cs = (tid & 1) * 32;
            const float* sp = stage + r2 * 68 + cs;
            uint4 ov[4];
            #pragma unroll
            for (int u = 0; u < 4; ++u) {
                uint32_t pk[4];
                #pragma unroll
                for (int e = 0; e < 4; ++e) {
                    __half2_raw h = __half2_raw(__floats2half2_rn(sp[u*8 + 2*e], sp[u*8 + 2*e + 1]));
                    pk[e] = h.x | ((uint32_t)h.y << 16);
                }
                ov[u] = make_uint4(pk[0], pk[1], pk[2], pk[3]);
            }
            uint4* dp = (uint4*)(g_B_E + (size_t)(c0 + r2) * KPAD + tau0 + p * 64 + cs);
            #pragma unroll
            for (int u = 0; u < 4; ++u) dp[u] = ov[u];
        }
        __syncthreads();
    }
}

// ---------------- conv GEMM (R10 best): merged N, 512 threads, cp.async 2-stage ----------------
#define CONV_SMEM (110592 + 1024)
__global__ __launch_bounds__(512, 1)
void conv_wmma_kernel(const float* __restrict__ conv_b) {
    extern __shared__ char smem[];
    float*  stage = (float*)smem;               // epilogue: [128][130]f
    float*  bias  = (float*)(smem + 110592);    // [256]

    const int tid = threadIdx.x;
    const int wid = tid >> 5;                   // 0..15
    const int wm = wid & 3, wn = wid >> 2;      // wm: 4 x 32 rows, wn: 4 x 64 cols
    const int r0 = blockIdx.x * 128;

    if (tid < 256) bias[tid] = conv_b[tid];

    const int arow_i = tid >> 2, aseg = (tid & 3) * 16;
    const int ar = r0 + arow_i, ab = ar / 9, am = ar - 9 * ab;
    const __half* xrow = g_xhf + (size_t)ab * 1024 + 32 * am + aseg;
    const int brow_i = tid >> 1, bseg = (tid & 1) * 32;
    const __half* brow = g_B_E + (size_t)brow_i * KPAD + bseg;

    const uint32_t sbase = smem_u32(smem);
    const uint32_t aoff = (uint32_t)(arow_i * 72 + aseg) * 2;
    const uint32_t boff = 18432 + (uint32_t)(brow_i * 72 + bseg) * 2;

    wmma::fragment<wmma::matrix_a, 16, 16, 16, __half, wmma::row_major> af[2];
    wmma::fragment<wmma::matrix_b, 16, 16, 16, __half, wmma::col_major> bf[4];
    wmma::fragment<wmma::accumulator, 16, 16, 16, float> acc[2][4];
    #pragma unroll
    for (int i = 0; i < 2; ++i)
        #pragma unroll
        for (int j = 0; j < 4; ++j)
            wmma::fill_fragment(acc[i][j], 0.0f);

    {
        #pragma unroll
        for (int q = 0; q < 2; ++q) cp_async16(sbase + aoff + q * 16, xrow + q * 8);
        #pragma unroll
        for (int q = 0; q < 4; ++q) cp_async16(sbase + boff + q * 16, brow + q * 8);
        CP_COMMIT();
    }

    for (int chunk = 0; chunk < 12; ++chunk) {
        if (chunk < 11) {
            uint32_t bufn = ((chunk + 1) & 1) * 55296;
            const __half* xs  = xrow + (chunk + 1) * 64;
            const __half* bs2 = brow + (chunk + 1) * 64;
            #pragma unroll
            for (int q = 0; q < 2; ++q) cp_async16(sbase + bufn + aoff + q * 16, xs + q * 8);
            #pragma unroll
            for (int q = 0; q < 4; ++q) cp_async16(sbase + bufn + boff + q * 16, bs2 + q * 8);
            CP_COMMIT();
            CP_WAIT(1);
        } else {
            CP_WAIT(0);
        }
        __syncthreads();
        __half* As = (__half*)(smem + (chunk & 1) * 55296);
        __half* Bs = As + 128 * 72;
        #pragma unroll
        for (int kk = 0; kk < 4; ++kk) {
            #pragma unroll
            for (int i = 0; i < 2; ++i)
                wmma::load_matrix_sync(af[i], As + (wm*32 + i*16) * 72 + kk*16, 72);
            #pragma unroll
            for (int j = 0; j < 4; ++j)
                wmma::load_matrix_sync(bf[j], Bs + (wn*64 + j*16) * 72 + kk*16, 72);
            #pragma unroll
            for (int i = 0; i < 2; ++i)
                #pragma unroll
                for (int j = 0; j < 4; ++j)
                    wmma::mma_sync(acc[i][j], af[i], bf[j], acc[i][j]);
        }
        __syncthreads();
    }

    const int b_first = r0 / 9;
    const int b_last  = (r0 + 127) / 9;
    for (int p = 0; p < 2; ++p) {
        if ((wn >> 1) == p) {
            #pragma unroll
            for (int i = 0; i < 2; ++i)
                #pragma unroll
                for (int j = 0; j < 4; ++j)
                    wmma::store_matrix_sync(stage + (wm*32 + i*16) * 130 + (wn & 1) * 64 + j*16,
                                            acc[i][j], 130, wmma::mem_row_major);
        }
        __syncthreads();
        for (int b = b_first; b <= b_last; ++b) {
            const int rbase = b * 9 - r0;
            float* dst = g_P2 + (size_t)b * 2304 + p * 1152;
            for (int j = tid; j < 1152; j += 512) {
                int cl = j / 9, m = j - 9 * cl;
                int rr = rbase + m;
                if (rr >= 0 && rr < 128)
                    dst[j] = stage[rr * 130 + cl] + bias[p * 128 + cl];
            }
        }
        __syncthreads();
    }
}

// ---------------- u_hat GEMM v4: spill fix (occ 4, 64-reg budget) ----------------
#define UHAT_SMEM (6144 + 6144 + 10240)
__global__ __launch_bounds__(256, 4)
void uhat_gemm_kernel() {
    extern __shared__ char smem[];
    __half* Aw = (__half*)smem;                  // [128][24]
    __half* Bw = (__half*)(smem + 6144);         // [128][24]
    float*  stg = (float*)(smem + 12288);        // per-warp [16][20]

    const int tid = threadIdx.x, wid = tid >> 5, lane = tid & 31;
    const int b0 = blockIdx.x * 128;
    const int g  = blockIdx.y;

    {
        int b_l = tid >> 1, capl = tid & 1;
        int b = b0 + b_l, cap = g * 2 + capl;
        const float4* pp = (const float4*)(g_P2 + (size_t)b * 2304 + cap * 8);
        float4 p0 = pp[0], p1 = pp[1];
        float sn = p0.x*p0.x + p0.y*p0.y + p0.z*p0.z + p0.w*p0.w
                 + p1.x*p1.x + p1.y*p1.y + p1.z*p1.z + p1.w*p1.w;
        float sc = (sn / (1.0f + sn)) * rsqrtf(sn + 1e-8f);
        __half2_raw h0 = __half2_raw(__floats2half2_rn(p0.x*sc, p0.y*sc));
        __half2_raw h1 = __half2_raw(__floats2half2_rn(p0.z*sc, p0.w*sc));
        __half2_raw h2 = __half2_raw(__floats2half2_rn(p1.x*sc, p1.y*sc));
        __half2_raw h3 = __half2_raw(__floats2half2_rn(p1.z*sc, p1.w*sc));
        *(uint4*)(Aw + b_l * 24 + capl * 8) =
            make_uint4(h0.x | ((uint32_t)h0.y << 16), h1.x | ((uint32_t)h1.y << 16),
                       h2.x | ((uint32_t)h2.y << 16), h3.x | ((uint32_t)h3.y << 16));
    }
    {
        int n = tid >> 1, hseg = (tid & 1) * 8;
        uint4 v = *(const uint4*)(g_Bpk + (size_t)g * 2048 + n * 16 + hseg);
        *(uint4*)(Bw + n * 24 + hseg) = v;
    }
    __syncthreads();

    wmma::fragment<wmma::matrix_a, 16, 16, 16, __half, wmma::row_major> af;
    wmma::load_matrix_sync(af, Aw + wid * 16 * 24, 24);
    float* ws = stg + wid * 320;
    const int orow = lane >> 1, ocs = (lane & 1) * 8;
    #pragma unroll
    for (int j = 0; j < 8; ++j) {
        wmma::fragment<wmma::matrix_b, 16, 16, 16, __half, wmma::col_major> bfj;
        wmma::load_matrix_sync(bfj, Bw + j * 16 * 24, 24);
        wmma::fragment<wmma::accumulator, 16, 16, 16, float> acc;
        wmma::fill_fragment(acc, 0.0f);
        wmma::mma_sync(acc, af, bfj, acc);
        wmma::store_matrix_sync(ws, acc, 20, wmma::mem_row_major);
        __syncwarp();
        {
            const float* sp = ws + orow * 20 + ocs;
            uint32_t pk[4];
            #pragma unroll
            for (int e = 0; e < 4; ++e) {
                __half2_raw h = __half2_raw(__floats2half2_rn(sp[2*e], sp[2*e + 1]));
                pk[e] = h.x | ((uint32_t)h.y << 16);
            }
            *(uint4*)(g_UH + (size_t)(b0 + wid * 16 + orow) * 18432 + g * 128 + j * 16 + ocs) =
                make_uint4(pk[0], pk[1], pk[2], pk[3]);
        }
        __syncwarp();
    }
}

// ---------------- routing v6: transposed cij for vectorized s_j ----------------
#define ROUT_SMEM (41472 + 4608 + 4672 + 2048 + 256)
__global__ __launch_bounds__(256, 4)
void routing_kernel(float* __restrict__ out, int nB) {
    extern __shared__ char smc[];
    __half* uhh = (__half*)smc;                  // [288][72]
    float* bij  = (float*)(smc + 41472);         // [1152]
    float* cijT = bij + 1152;                    // [4][292]
    float* part = cijT + 4 * 292;                // [512]
    float* vv   = part + 512;                    // [64]
    const int tid = threadIdx.x;
    const int b = blockIdx.x;

    const uint4* src = (const uint4*)(g_UH + (size_t)b * 18432);
    #pragma unroll
    for (int it = 0; it < 9; ++it) {
        int vi = tid + it * 256;
        uint4 v = src[vi];
        int cc = vi >> 3, seg = (vi & 7) * 8;
        *(uint4*)(uhh + cc * 72 + seg) = v;
    }
    __syncthreads();

    const int prt = tid >> 5, op = tid & 31;
    const int dd  = op >> 3;

    for (int r = 0; r < 3; ++r) {
        if (r > 0) {
            for (int j = tid; j < NCAP; j += 256) {
                float b0 = bij[j*4+0], b1 = bij[j*4+1], b2 = bij[j*4+2], b3 = bij[j*4+3];
                float mx = fmaxf(fmaxf(b0, b1), fmaxf(b2, b3));
                float e0 = __expf(b0-mx), e1 = __expf(b1-mx);
                float e2 = __expf(b2-mx), e3 = __expf(b3-mx);
                float inv = 1.0f / (e0 + e1 + e2 + e3);
                cijT[0*292 + j] = e0*inv; cijT[1*292 + j] = e1*inv;
                cijT[2*292 + j] = e2*inv; cijT[3*292 + j] = e3*inv;
            }
            __syncthreads();
        }
        {
            float a0 = 0.0f, a1 = 0.0f;
            int cb = prt * 36;
            if (r == 0) {
                #pragma unroll 4
                for (int cc = cb; cc < cb + 36; ++cc) {
                    float2 f = __half22float2(*(const __half2*)(uhh + cc * 72 + 2 * op));
                    a0 += f.x; a1 += f.y;
                }
                a0 *= 0.25f; a1 *= 0.25f;
            } else {
                const float* cwp = cijT + dd * 292 + cb;
                #pragma unroll
                for (int q = 0; q < 9; ++q) {
                    float4 cw = *(const float4*)(cwp + q * 4);
                    int cc = cb + q * 4;
                    float2 f0 = __half22float2(*(const __half2*)(uhh + (cc+0) * 72 + 2 * op));
                    float2 f1 = __half22float2(*(const __half2*)(uhh + (cc+1) * 72 + 2 * op));
                    float2 f2 = __half22float2(*(const __half2*)(uhh + (cc+2) * 72 + 2 * op));
                    float2 f3 = __half22float2(*(const __half2*)(uhh + (cc+3) * 72 + 2 * op));
                    a0 += cw.x * f0.x + cw.y * f1.x + cw.z * f2.x + cw.w * f3.x;
                    a1 += cw.x * f0.y + cw.y * f1.y + cw.z * f2.y + cw.w * f3.y;
                }
            }
            part[prt * 64 + 2 * op]     = a0;
            part[prt * 64 + 2 * op + 1] = a1;
        }
        __syncthreads();
        if (tid < 64) {
            float s = 0.0f;
            #pragma unroll
            for (int p = 0; p < 8; ++p) s += part[p * 64 + tid];
            float sq = s * s;
            #pragma unroll
            for (int off = 8; off >= 1; off >>= 1)
                sq += __shfl_xor_sync(0xffffffffu, sq, off);
            float scale = (sq / (1.0f + sq)) * rsqrtf(sq + 1e-8f);
            vv[tid] = s * scale;
        }
        __syncthreads();
        if (r < 2) {
            for (int i = tid; i < 1152; i += 256) {
                int cc = i >> 2, d2 = i & 3;
                const __half2* up = (const __half2*)(uhh + cc * 72 + d2 * 16);
                const float* vp = vv + d2 * 16;
                float agr = 0.0f;
                #pragma unroll
                for (int e = 0; e < 8; ++e) {
                    float2 f = __half22float2(up[e]);
                    agr += f.x * vp[2*e] + f.y * vp[2*e + 1];
                }
                if (r == 0) bij[i] = agr; else bij[i] += agr;
            }
            __syncthreads();
        }
    }
    if (tid < 4) {
        float sn = 0.0f;
        #pragma unroll
        for (int o = 0; o < 16; ++o) { float t = vv[tid*16+o]; sn += t*t; }
        out[b * 4 + tid] = sqrtf(sn);
    }
    float* out_cij = out + (size_t)nB * 4 + (size_t)b * 1152;
    for (int i = tid; i < 1152; i += 256)
        out_cij[i] = cijT[(i & 3) * 292 + (i >> 2)];
}

// ---------------- launcher ----------------
extern "C" void kernel_launch(void* const* d_in, const int* in_sizes, int n_in,
                              void* d_out, int out_size) {
    const float* x      = (const float*)d_in[0];
    const float* a      = (const float*)d_in[1];
    const float* w      = (const float*)d_in[2];
    const float* conv_w = (const float*)d_in[3];
    const float* conv_b = (const float*)d_in[4];
    const float* W_caps = (const float*)d_in[5];
    int nB = in_sizes[0] / NPOS;   // 4096

    cudaFuncSetAttribute(conv_wmma_kernel, cudaFuncAttributeMaxDynamicSharedMemorySize, CONV_SMEM);
    cudaFuncSetAttribute(routing_kernel,   cudaFuncAttributeMaxDynamicSharedMemorySize, ROUT_SMEM);

    pre1_kernel<<<19840, 256>>>(x, a, w, conv_w, W_caps);
    w2t_kernel<<<6144, 256>>>();
    compose_wmma_kernel<<<dim3(2, 6), 256, COMP_SMEM>>>();
    conv_wmma_kernel<<<nB * 9 / 128, 512, CONV_SMEM>>>(conv_b);
    uhat_gemm_kernel<<<dim3(nB / 128, 144), 256, UHAT_SMEM>>>();
    routing_kernel<<<nB, 256, ROUT_SMEM>>>((float*)d_out, nB);
}